// round 1
// baseline (speedup 1.0000x reference)
#include <cuda_runtime.h>
#include <cstdint>

// MultiLevelEmbedding: out[b,t,:] = emb_tables[level_ids[b,t], token_ids[b,t], :]
//                                   + level_embed[level_ids[b,t], :]
// B=64, T=1024, L=4, VOCAB=258, D=512 (float32).
// Memory-bound: 128 MiB output write (DRAM), gathers hit L2 (table = 2.1 MB).

#define D_DIM       512
#define D_VEC       (D_DIM / 4)     // 128 float4 per row
#define VOCAB_SZ    258
#define N_POS       (64 * 1024)     // B*T
#define TOTAL_VEC   (N_POS * D_VEC) // 8,388,608 float4

// 1 = indices are int64, 0 = int32. Decided by detector kernel each launch.
__device__ int g_idx_is64;

// token_ids values are in [0, 258): if stored as int64 (little-endian), every
// odd 32-bit word is 0. If int32, odd words are random token values
// (P(all 64 zero) ~ (1/258)^64 ~ 0).
__global__ void detect_idx_dtype_kernel(const uint32_t* __restrict__ tok_raw) {
    if (threadIdx.x == 0 && blockIdx.x == 0) {
        int is64 = 1;
        #pragma unroll
        for (int i = 0; i < 64; ++i) {
            if (tok_raw[2 * i + 1] != 0u) { is64 = 0; break; }
        }
        g_idx_is64 = is64;
    }
}

__global__ __launch_bounds__(256)
void multi_level_embedding_kernel(const void* __restrict__ level_ids_raw,
                                  const void* __restrict__ token_ids_raw,
                                  const float4* __restrict__ emb_tables,
                                  const float4* __restrict__ level_embed,
                                  float4* __restrict__ out) {
    const int idx = blockIdx.x * 256 + threadIdx.x;   // one float4 per thread
    if (idx >= TOTAL_VEC) return;

    const int pos = idx >> 7;        // which (b,t) position
    const int c   = idx & (D_VEC - 1);

    const int is64 = g_idx_is64;     // uniform branch, L1-broadcast load

    long long lid, tid;
    if (is64) {
        lid = ((const long long*)level_ids_raw)[pos];   // same addr across warp
        tid = ((const long long*)token_ids_raw)[pos];
    } else {
        lid = ((const int*)level_ids_raw)[pos];
        tid = ((const int*)token_ids_raw)[pos];
    }

    const long long row = lid * VOCAB_SZ + tid;         // row in stacked tables
    const float4 a = __ldg(&emb_tables[row * D_VEC + c]);      // L2-resident
    const float4 b = __ldg(&level_embed[lid * D_VEC + c]);     // L1-resident

    float4 r;
    r.x = a.x + b.x;
    r.y = a.y + b.y;
    r.z = a.z + b.z;
    r.w = a.w + b.w;
    out[idx] = r;                                       // STG.128, DRAM-bound
}

extern "C" void kernel_launch(void* const* d_in, const int* in_sizes, int n_in,
                              void* d_out, int out_size) {
    const void*   level_ids  = d_in[0];
    const void*   token_ids  = d_in[1];
    const float4* emb_tables = (const float4*)d_in[2];
    const float4* level_emb  = (const float4*)d_in[3];
    float4*       out        = (float4*)d_out;

    detect_idx_dtype_kernel<<<1, 32>>>((const uint32_t*)token_ids);

    const int blocks = (TOTAL_VEC + 255) / 256;         // 32768
    multi_level_embedding_kernel<<<blocks, 256>>>(level_ids, token_ids,
                                                  emb_tables, level_emb, out);
}

// round 2
// speedup vs baseline: 1.5112x; 1.5112x over previous
#include <cuda_runtime.h>
#include <cstdint>

// MultiLevelEmbedding: out[b,t,:] = emb_tables[level_ids[b,t], token_ids[b,t], :]
//                                   + level_embed[level_ids[b,t], :]
// B=64, T=1024, L=4, VOCAB=258, D=512 (float32).
//
// R2: single launch. One warp per (b,t) row; each lane handles 4 float4
// (lane, lane+32, lane+64, lane+96) -> 8 independent LDG.128 in flight per
// lane before stores. Index dtype (int64 vs int32) detected in-kernel via a
// per-warp ballot over the odd 32-bit words of token_ids (all-zero <=> int64;
// values < 258 so P(false int64 on int32 data) ~ (1/258)^32 ~ 0).

#define D_VEC     128               // float4 per row (D=512)
#define VOCAB_SZ  258
#define N_POS     (64 * 1024)       // B*T rows

__global__ __launch_bounds__(256)
void multi_level_embedding_kernel(const void* __restrict__ level_ids_raw,
                                  const void* __restrict__ token_ids_raw,
                                  const float4* __restrict__ emb_tables,
                                  const float4* __restrict__ level_embed,
                                  float4* __restrict__ out) {
    const int lane = threadIdx.x & 31;
    const int pos  = (blockIdx.x * 256 + threadIdx.x) >> 5;   // warp id = row

    // ---- dtype detection (warp-uniform, 1 LDG + ballot) ----
    const uint32_t* tr = (const uint32_t*)token_ids_raw;
    const unsigned nz  = __ballot_sync(0xffffffffu, tr[2 * lane + 1] != 0u);
    const bool is64    = (nz == 0u);

    // ---- warp-uniform index loads (broadcast) ----
    long long lid, tid;
    if (is64) {
        lid = ((const long long*)level_ids_raw)[pos];
        tid = ((const long long*)token_ids_raw)[pos];
    } else {
        lid = ((const int*)level_ids_raw)[pos];
        tid = ((const int*)token_ids_raw)[pos];
    }

    const float4* __restrict__ arow = emb_tables + (lid * VOCAB_SZ + tid) * D_VEC;
    const float4* __restrict__ brow = level_embed + lid * D_VEC;
    float4* __restrict__       orow = out + (long long)pos * D_VEC;

    // ---- 8 independent loads first (MLP), then add + store ----
    float4 a0 = __ldg(arow + lane);
    float4 a1 = __ldg(arow + lane + 32);
    float4 a2 = __ldg(arow + lane + 64);
    float4 a3 = __ldg(arow + lane + 96);
    float4 b0 = __ldg(brow + lane);
    float4 b1 = __ldg(brow + lane + 32);
    float4 b2 = __ldg(brow + lane + 64);
    float4 b3 = __ldg(brow + lane + 96);

    float4 r;
    r.x = a0.x + b0.x; r.y = a0.y + b0.y; r.z = a0.z + b0.z; r.w = a0.w + b0.w;
    orow[lane] = r;
    r.x = a1.x + b1.x; r.y = a1.y + b1.y; r.z = a1.z + b1.z; r.w = a1.w + b1.w;
    orow[lane + 32] = r;
    r.x = a2.x + b2.x; r.y = a2.y + b2.y; r.z = a2.z + b2.z; r.w = a2.w + b2.w;
    orow[lane + 64] = r;
    r.x = a3.x + b3.x; r.y = a3.y + b3.y; r.z = a3.z + b3.z; r.w = a3.w + b3.w;
    orow[lane + 96] = r;
}

extern "C" void kernel_launch(void* const* d_in, const int* in_sizes, int n_in,
                              void* d_out, int out_size) {
    const void*   level_ids  = d_in[0];
    const void*   token_ids  = d_in[1];
    const float4* emb_tables = (const float4*)d_in[2];
    const float4* level_emb  = (const float4*)d_in[3];
    float4*       out        = (float4*)d_out;

    // 1 warp per row, 8 warps per block -> N_POS/8 blocks
    const int blocks = N_POS / 8;   // 8192
    multi_level_embedding_kernel<<<blocks, 256>>>(level_ids, token_ids,
                                                  emb_tables, level_emb, out);
}

// round 3
// speedup vs baseline: 1.6199x; 1.0719x over previous
#include <cuda_runtime.h>
#include <cstdint>

// MultiLevelEmbedding: out[b,t,:] = emb_tables[level_ids[b,t], token_ids[b,t], :]
//                                   + level_embed[level_ids[b,t], :]
// B=64, T=1024, L=4, VOCAB=258, D=512 (float32).
//
// R3: two-kernel plan.
//  1) fuse_kernel: fused[l][v][:] = emb_tables[l][v][:] + level_embed[l][:]
//     (2.1 MB scratch in a __device__ array; ~2-3 us)
//  2) gather_kernel: pure gather-copy from fused table. One warp handles 2
//     rows, 4 float4 per lane per row -> 8 independent LDG.128 in flight.
//     Output stored with __stcs (evict-first) so the 128 MB stream doesn't
//     evict the hot 2.1 MB fused table from L2.
// Index dtype (int64 vs int32) detected in-kernel via per-warp ballot over
// odd 32-bit words of token_ids (values < 258 => odd words all-zero iff i64).

#define D_VEC     128                 // float4 per row (D=512)
#define VOCAB_SZ  258
#define L_LVL     4
#define N_POS     (64 * 1024)         // B*T rows
#define FUSED_N   (L_LVL * VOCAB_SZ * D_VEC)   // 132096 float4 = 2.1 MB

__device__ float4 g_fused[FUSED_N];

__global__ __launch_bounds__(256)
void fuse_kernel(const float4* __restrict__ emb_tables,
                 const float4* __restrict__ level_embed) {
    const int i = blockIdx.x * 256 + threadIdx.x;   // grid covers FUSED_N exactly
    const int c   = i & (D_VEC - 1);
    const int row = i >> 7;                         // l*VOCAB + v
    const int l   = row / VOCAB_SZ;

    const float4 a = __ldg(emb_tables + i);
    const float4 b = __ldg(level_embed + l * D_VEC + c);
    float4 r;
    r.x = a.x + b.x; r.y = a.y + b.y; r.z = a.z + b.z; r.w = a.w + b.w;
    g_fused[i] = r;
}

__global__ __launch_bounds__(256)
void gather_kernel(const void* __restrict__ level_ids_raw,
                   const void* __restrict__ token_ids_raw,
                   float4* __restrict__ out) {
    const int lane = threadIdx.x & 31;
    const int warp = (blockIdx.x * 256 + threadIdx.x) >> 5;
    const int pos0 = warp * 2;                      // this warp's 2 rows
    const int pos1 = pos0 + 1;

    // ---- dtype detection (1 LDG + ballot, warp-uniform result) ----
    const uint32_t* tr = (const uint32_t*)token_ids_raw;
    const unsigned nz  = __ballot_sync(0xffffffffu, tr[2 * lane + 1] != 0u);
    const bool is64    = (nz == 0u);

    // ---- warp-uniform index loads (broadcast) ----
    long long l0, t0, l1, t1;
    if (is64) {
        l0 = ((const long long*)level_ids_raw)[pos0];
        t0 = ((const long long*)token_ids_raw)[pos0];
        l1 = ((const long long*)level_ids_raw)[pos1];
        t1 = ((const long long*)token_ids_raw)[pos1];
    } else {
        l0 = ((const int*)level_ids_raw)[pos0];
        t0 = ((const int*)token_ids_raw)[pos0];
        l1 = ((const int*)level_ids_raw)[pos1];
        t1 = ((const int*)token_ids_raw)[pos1];
    }

    const float4* __restrict__ r0 = g_fused + (l0 * VOCAB_SZ + t0) * D_VEC;
    const float4* __restrict__ r1 = g_fused + (l1 * VOCAB_SZ + t1) * D_VEC;
    float4* __restrict__ o0 = out + (long long)pos0 * D_VEC;
    float4* __restrict__ o1 = out + (long long)pos1 * D_VEC;

    // ---- 8 independent loads first (MLP), then streaming stores ----
    float4 a0 = __ldg(r0 + lane);
    float4 a1 = __ldg(r0 + lane + 32);
    float4 a2 = __ldg(r0 + lane + 64);
    float4 a3 = __ldg(r0 + lane + 96);
    float4 b0 = __ldg(r1 + lane);
    float4 b1 = __ldg(r1 + lane + 32);
    float4 b2 = __ldg(r1 + lane + 64);
    float4 b3 = __ldg(r1 + lane + 96);

    __stcs(o0 + lane,      a0);
    __stcs(o0 + lane + 32, a1);
    __stcs(o0 + lane + 64, a2);
    __stcs(o0 + lane + 96, a3);
    __stcs(o1 + lane,      b0);
    __stcs(o1 + lane + 32, b1);
    __stcs(o1 + lane + 64, b2);
    __stcs(o1 + lane + 96, b3);
}

extern "C" void kernel_launch(void* const* d_in, const int* in_sizes, int n_in,
                              void* d_out, int out_size) {
    const void*   level_ids  = d_in[0];
    const void*   token_ids  = d_in[1];
    const float4* emb_tables = (const float4*)d_in[2];
    const float4* level_emb  = (const float4*)d_in[3];
    float4*       out        = (float4*)d_out;

    // Prologue: build fused table (132096 float4 / 256 = 516 blocks exactly).
    fuse_kernel<<<FUSED_N / 256, 256>>>(emb_tables, level_emb);

    // Main: 2 rows per warp, 8 warps per block -> N_POS/16 blocks = 4096.
    gather_kernel<<<N_POS / 16, 256>>>(level_ids, token_ids, out);
}